// round 1
// baseline (speedup 1.0000x reference)
#include <cuda_runtime.h>
#include <math.h>

// ---------------------------------------------------------------------------
// PhysicsGuidedAttentionCorrected
// B=8, N=1024, C=256, NUM_HEADS=8, hd=32
// inputs: x[8,1024,256], elevation[8,1024], u_wind[8,64,64], v_wind[8,64,64],
//         w_qkv[768,256], w_proj[256,256], b_proj[256], alpha, beta
// output: [8,1024,256] f32
// ---------------------------------------------------------------------------

#define B_ 8
#define N_ 1024
#define C_ 256
#define NH_ 8
#define HD_ 32

// scratch (device globals; no allocations allowed)
__device__ float g_qkv[B_ * N_ * 3 * C_];   // [8192, 768], layout (q|k|v) x head x hd
__device__ float g_attn[B_ * N_ * C_];      // [8192, 256], head-major per row
__device__ float g_ws[B_ * N_];             // pooled wind strength

// ---------------------------------------------------------------------------
// wind strength: 2x2 avg pool of sqrt(u^2+v^2+1e-8) over [64,64] -> [32,32]=1024
// ---------------------------------------------------------------------------
__global__ void wind_kernel(const float* __restrict__ u,
                            const float* __restrict__ v,
                            float* __restrict__ ws) {
    int t = blockIdx.x * blockDim.x + threadIdx.x;   // 8192 total
    if (t >= B_ * N_) return;
    int b = t >> 10;
    int n = t & 1023;
    int r = n >> 5;
    int c = n & 31;
    const float* ub = u + b * 4096;
    const float* vb = v + b * 4096;
    float s = 0.0f;
#pragma unroll
    for (int dr = 0; dr < 2; ++dr)
#pragma unroll
        for (int dc = 0; dc < 2; ++dc) {
            int idx = (2 * r + dr) * 64 + (2 * c + dc);
            float uu = ub[idx], vv = vb[idx];
            s += sqrtf(uu * uu + vv * vv + 1e-8f);
        }
    ws[t] = s * 0.25f;
}

// ---------------------------------------------------------------------------
// SGEMM: C[m,n] = sum_k A[m,k] * B[n,k]  (+ bias[n])
// A [M,K] row-major, B [N,K] row-major. M%128==0, N%128==0, K%16==0.
// 128x128 block tile, BK=16, 256 threads, 8x8 micro-tile.
// ---------------------------------------------------------------------------
template <bool HAS_BIAS>
__global__ __launch_bounds__(256, 2)
void gemm_abt(const float* __restrict__ A, const float* __restrict__ B,
              const float* __restrict__ bias, float* __restrict__ C,
              int M, int N, int K) {
    __shared__ __align__(16) float As[16][132];
    __shared__ __align__(16) float Bs[16][132];

    const int tid = threadIdx.x;
    const int tx = tid & 15;
    const int ty = tid >> 4;
    const int bx = blockIdx.x;     // N tile
    const int by = blockIdx.y;     // M tile

    const float* Ag = A + (size_t)by * 128 * K;
    const float* Bg = B + (size_t)bx * 128 * K;

    float acc[8][8];
#pragma unroll
    for (int r = 0; r < 8; ++r)
#pragma unroll
        for (int c = 0; c < 8; ++c) acc[r][c] = 0.0f;

    const int lrow = tid >> 2;          // 0..63
    const int lk = (tid & 3) * 4;       // 0,4,8,12

    for (int kb = 0; kb < K; kb += 16) {
#pragma unroll
        for (int h = 0; h < 2; ++h) {
            int row = lrow + h * 64;
            float4 a = *reinterpret_cast<const float4*>(Ag + (size_t)row * K + kb + lk);
            As[lk + 0][row] = a.x; As[lk + 1][row] = a.y;
            As[lk + 2][row] = a.z; As[lk + 3][row] = a.w;
            float4 b = *reinterpret_cast<const float4*>(Bg + (size_t)row * K + kb + lk);
            Bs[lk + 0][row] = b.x; Bs[lk + 1][row] = b.y;
            Bs[lk + 2][row] = b.z; Bs[lk + 3][row] = b.w;
        }
        __syncthreads();

#pragma unroll
        for (int k = 0; k < 16; ++k) {
            float4 a0 = *reinterpret_cast<const float4*>(&As[k][8 * ty]);
            float4 a1 = *reinterpret_cast<const float4*>(&As[k][8 * ty + 4]);
            float4 b0 = *reinterpret_cast<const float4*>(&Bs[k][8 * tx]);
            float4 b1 = *reinterpret_cast<const float4*>(&Bs[k][8 * tx + 4]);
            float av[8] = {a0.x, a0.y, a0.z, a0.w, a1.x, a1.y, a1.z, a1.w};
            float bv[8] = {b0.x, b0.y, b0.z, b0.w, b1.x, b1.y, b1.z, b1.w};
#pragma unroll
            for (int r = 0; r < 8; ++r)
#pragma unroll
                for (int c = 0; c < 8; ++c)
                    acc[r][c] = fmaf(av[r], bv[c], acc[r][c]);
        }
        __syncthreads();
    }

    float bv[8];
    if (HAS_BIAS) {
#pragma unroll
        for (int c = 0; c < 8; ++c) bv[c] = bias[bx * 128 + 8 * tx + c];
    }
#pragma unroll
    for (int r = 0; r < 8; ++r) {
        int grow = by * 128 + 8 * ty + r;
        float* Cp = C + (size_t)grow * N + bx * 128 + 8 * tx;
        float4 o0, o1;
        if (HAS_BIAS) {
            o0 = make_float4(acc[r][0] + bv[0], acc[r][1] + bv[1],
                             acc[r][2] + bv[2], acc[r][3] + bv[3]);
            o1 = make_float4(acc[r][4] + bv[4], acc[r][5] + bv[5],
                             acc[r][6] + bv[6], acc[r][7] + bv[7]);
        } else {
            o0 = make_float4(acc[r][0], acc[r][1], acc[r][2], acc[r][3]);
            o1 = make_float4(acc[r][4], acc[r][5], acc[r][6], acc[r][7]);
        }
        *reinterpret_cast<float4*>(Cp) = o0;
        *reinterpret_cast<float4*>(Cp + 4) = o1;
    }
}

// ---------------------------------------------------------------------------
// fused attention: one block = (batch b, head h, 64-query chunk)
// flash-style online softmax over 16 key tiles of 64, bias computed inline.
// 256 threads: tx=tid&15 (4 key cols), ty=tid>>4 (4 query rows).
// ---------------------------------------------------------------------------
__global__ __launch_bounds__(256)
void attn_kernel(const float* __restrict__ qkv,
                 const float* __restrict__ elev,
                 const float* __restrict__ ws,
                 const float* __restrict__ alpha_p,
                 const float* __restrict__ beta_p,
                 float* __restrict__ outp) {
    __shared__ __align__(16) float Qs[32][68];   // [d][i]
    __shared__ __align__(16) float Ks[32][68];   // [d][j]
    __shared__ __align__(16) float Vs[64][36];   // [j][d]
    __shared__ __align__(16) float Ps[64][68];   // [j][i]
    __shared__ float eQ[64], wQ[64], eK[64], wK[64];

    const int tid = threadIdx.x;
    const int tx = tid & 15;
    const int ty = tid >> 4;
    const int qc = blockIdx.x;     // 0..15
    const int h  = blockIdx.y;     // 0..7
    const int b  = blockIdx.z;     // 0..7

    const float alpha = *alpha_p;
    const float beta  = *beta_p;
    const float scale = 0.17677669529663687f;   // 1/sqrt(32)

    const int qrow0 = b * N_ + qc * 64;

    // load Q tile (transposed into Qs[d][i])
#pragma unroll
    for (int it = 0; it < 2; ++it) {
        int idx = tid + it * 256;
        int i = idx >> 3;
        int dq = (idx & 7) * 4;
        float4 q = *reinterpret_cast<const float4*>(
            qkv + (size_t)(qrow0 + i) * 768 + h * HD_ + dq);
        Qs[dq + 0][i] = q.x; Qs[dq + 1][i] = q.y;
        Qs[dq + 2][i] = q.z; Qs[dq + 3][i] = q.w;
    }
    if (tid < 64) {
        eQ[tid] = elev[qrow0 + tid];
        wQ[tid] = ws[qrow0 + tid];
    }
    __syncthreads();

    float eQr[4], wQr[4];
#pragma unroll
    for (int r = 0; r < 4; ++r) { eQr[r] = eQ[4 * ty + r]; wQr[r] = wQ[4 * ty + r]; }

    float m[4], l[4], acc[4][2];
#pragma unroll
    for (int r = 0; r < 4; ++r) {
        m[r] = -1e30f; l[r] = 0.0f; acc[r][0] = 0.0f; acc[r][1] = 0.0f;
    }

#pragma unroll 1
    for (int kt = 0; kt < 16; ++kt) {
        __syncthreads();   // protect Ks/Vs/Ps reuse vs previous iteration reads
        const int krow0 = b * N_ + kt * 64;

        // load K (transposed) and V (natural)
#pragma unroll
        for (int it = 0; it < 2; ++it) {
            int idx = tid + it * 256;
            int i = idx >> 3;
            int dq = (idx & 7) * 4;
            size_t base = (size_t)(krow0 + i) * 768 + h * HD_ + dq;
            float4 kv = *reinterpret_cast<const float4*>(qkv + base + 256);
            Ks[dq + 0][i] = kv.x; Ks[dq + 1][i] = kv.y;
            Ks[dq + 2][i] = kv.z; Ks[dq + 3][i] = kv.w;
            float4 vv = *reinterpret_cast<const float4*>(qkv + base + 512);
            *reinterpret_cast<float4*>(&Vs[i][dq]) = vv;
        }
        if (tid < 64) {
            eK[tid] = elev[krow0 + tid];
            wK[tid] = ws[krow0 + tid];
        }
        __syncthreads();

        // S = Q K^T (64x64 tile, 4x4 per thread)
        float s[4][4];
#pragma unroll
        for (int r = 0; r < 4; ++r)
#pragma unroll
            for (int c = 0; c < 4; ++c) s[r][c] = 0.0f;

#pragma unroll
        for (int d = 0; d < 32; ++d) {
            float4 qa = *reinterpret_cast<const float4*>(&Qs[d][4 * ty]);
            float4 ka = *reinterpret_cast<const float4*>(&Ks[d][4 * tx]);
            float qv[4] = {qa.x, qa.y, qa.z, qa.w};
            float kv[4] = {ka.x, ka.y, ka.z, ka.w};
#pragma unroll
            for (int r = 0; r < 4; ++r)
#pragma unroll
                for (int c = 0; c < 4; ++c)
                    s[r][c] = fmaf(qv[r], kv[c], s[r][c]);
        }

        // scale + physics bias
        float eKc[4], wKc[4];
#pragma unroll
        for (int c = 0; c < 4; ++c) { eKc[c] = eK[4 * tx + c]; wKc[c] = wK[4 * tx + c]; }
#pragma unroll
        for (int r = 0; r < 4; ++r)
#pragma unroll
            for (int c = 0; c < 4; ++c) {
                float ed = (eKc[c] - eQr[r]) * 1e-3f;   // /H_SCALE
                ed = fmaxf(ed, 0.0f);                   // relu
                float z = (wQr[r] + wKc[c]) * 0.5f - 5.0f;
                float wf = 1.0f / (1.0f + __expf(-z));  // sigmoid
                float bia = -alpha * ed * (1.0f - beta * wf);
                bia = fminf(fmaxf(bia, -10.0f), 0.0f);
                s[r][c] = fmaf(s[r][c], scale, bia);
            }

        // online softmax (row stats reduced over the 16-lane tx group)
#pragma unroll
        for (int r = 0; r < 4; ++r) {
            float mt = fmaxf(fmaxf(s[r][0], s[r][1]), fmaxf(s[r][2], s[r][3]));
#pragma unroll
            for (int o = 1; o < 16; o <<= 1)
                mt = fmaxf(mt, __shfl_xor_sync(0xffffffffu, mt, o));
            float mn = fmaxf(m[r], mt);
            float sc = __expf(m[r] - mn);
            float rs = 0.0f;
#pragma unroll
            for (int c = 0; c < 4; ++c) {
                float p = __expf(s[r][c] - mn);
                s[r][c] = p;
                rs += p;
            }
#pragma unroll
            for (int o = 1; o < 16; o <<= 1)
                rs += __shfl_xor_sync(0xffffffffu, rs, o);
            l[r] = l[r] * sc + rs;
            m[r] = mn;
            acc[r][0] *= sc;
            acc[r][1] *= sc;
        }

        // P -> smem (transposed: Ps[j][i])
#pragma unroll
        for (int r = 0; r < 4; ++r)
#pragma unroll
            for (int c = 0; c < 4; ++c)
                Ps[4 * tx + c][4 * ty + r] = s[r][c];
        __syncthreads();

        // O += P @ V : thread owns rows 4ty..4ty+3, dims 2tx..2tx+1
#pragma unroll 16
        for (int j = 0; j < 64; ++j) {
            float4 pa = *reinterpret_cast<const float4*>(&Ps[j][4 * ty]);
            float2 va = *reinterpret_cast<const float2*>(&Vs[j][2 * tx]);
            acc[0][0] = fmaf(pa.x, va.x, acc[0][0]);
            acc[0][1] = fmaf(pa.x, va.y, acc[0][1]);
            acc[1][0] = fmaf(pa.y, va.x, acc[1][0]);
            acc[1][1] = fmaf(pa.y, va.y, acc[1][1]);
            acc[2][0] = fmaf(pa.z, va.x, acc[2][0]);
            acc[2][1] = fmaf(pa.z, va.y, acc[2][1]);
            acc[3][0] = fmaf(pa.w, va.x, acc[3][0]);
            acc[3][1] = fmaf(pa.w, va.y, acc[3][1]);
        }
    }

    // epilogue: divide by l, write [B,N, h*32 + d] layout (matches reference
    // transpose(0,2,1,3).reshape(B,N,C))
#pragma unroll
    for (int r = 0; r < 4; ++r) {
        float inv = 1.0f / l[r];
        int orow = qrow0 + 4 * ty + r;
        float* op = outp + (size_t)orow * C_ + h * HD_ + 2 * tx;
        op[0] = acc[r][0] * inv;
        op[1] = acc[r][1] * inv;
    }
}

// ---------------------------------------------------------------------------
// launch
// ---------------------------------------------------------------------------
extern "C" void kernel_launch(void* const* d_in, const int* in_sizes, int n_in,
                              void* d_out, int out_size) {
    const float* x     = (const float*)d_in[0];
    const float* elev  = (const float*)d_in[1];
    const float* uw    = (const float*)d_in[2];
    const float* vw    = (const float*)d_in[3];
    const float* wqkv  = (const float*)d_in[4];
    const float* wproj = (const float*)d_in[5];
    const float* bproj = (const float*)d_in[6];
    const float* alpha = (const float*)d_in[7];
    const float* beta  = (const float*)d_in[8];
    float* out = (float*)d_out;

    float *qkv_p, *attn_p, *ws_p;
    cudaGetSymbolAddress((void**)&qkv_p, g_qkv);
    cudaGetSymbolAddress((void**)&attn_p, g_attn);
    cudaGetSymbolAddress((void**)&ws_p, g_ws);

    // 1) wind strength
    wind_kernel<<<32, 256>>>(uw, vw, ws_p);

    // 2) qkv = x @ w_qkv^T : [8192,256] x [768,256]^T -> [8192,768]
    gemm_abt<false><<<dim3(768 / 128, 8192 / 128), 256>>>(
        x, wqkv, nullptr, qkv_p, 8192, 768, 256);

    // 3) fused biased attention -> g_attn [8192,256]
    attn_kernel<<<dim3(16, NH_, B_), 256>>>(qkv_p, elev, ws_p, alpha, beta, attn_p);

    // 4) out = attn @ w_proj^T + b_proj
    gemm_abt<true><<<dim3(256 / 128, 8192 / 128), 256>>>(
        attn_p, wproj, bproj, out, 8192, 256, 256);
}